// round 15
// baseline (speedup 1.0000x reference)
#include <cuda_runtime.h>
#include <stdint.h>

// Fixed problem shapes
#define BQ 2
#define NQ 16384
#define SQ 4096
#define CQ 64
#define NS 32
#define OUTC 67
#define NCELL 1000            // 10x10x10 grid, cell = radius = 0.1
#define HB 64                 // wide hist/scatter blocks
#define NTILE 2048            // transpose tiles (512 n x 2 c x 2 b)
#define WARPS_Q 4             // warps per query block; each warp = 2 centers
#define CENTERS_PB (WARPS_Q * 2)              // 8 centers per block
#define QBLOCKS (BQ * SQ / CENTERS_PB)        // 1024 query blocks
#define STP 17                // float4 row pitch in stage (conflict-free)
#define CPB (BQ * SQ / HB)    // centers per hist/scatter block = 128
#define MW (NQ / 32)          // mask words per center = 512

// Device scratch (no allocations allowed). Count arrays start zero (static
// init) and are re-zeroed by k2 each replay -> stateless under graph replay.
__device__ float4 g_xyzp[BQ * NQ];                  // packed xyz, cell id in .w
__device__ float4 g_sorted[BQ * NQ];                // cell-sorted xyz, orig idx in .w
__device__ float4 g_cxyz[BQ * SQ];                  // packed centers, cell id in .w
__device__ float4 g_csorted[BQ * SQ];               // cell-sorted centers, orig s in .w
__device__ float  g_featT[(size_t)BQ * NQ * CQ];    // features [B,N,C]
__device__ int    g_cellcnt[BQ * NCELL];            // point histogram
__device__ int    g_cellstart[BQ * (NCELL + 1)];    // point exclusive prefix
__device__ int    g_cellfill[BQ * NCELL];           // point scatter cursors
__device__ int    g_ccnt[BQ * NCELL];               // center histogram
__device__ int    g_cfill[BQ * NCELL];              // center scatter cursors

__device__ __forceinline__ int cell_of(float v) {
    int c = (int)(v * 10.0f);
    return min(9, max(0, c));
}

// one 32x32 transpose tile of [B,C,N] -> [B,N,C]; id in [0, NTILE)
__device__ __forceinline__ void transpose_tile(const float* __restrict__ feat, int id) {
    __shared__ float tile[32][33];
    int n0 = (id & 511) * 32;
    int c0 = ((id >> 9) & 1) * 32;
    int b  = id >> 10;
    int tx = threadIdx.x & 31;
    int ty = threadIdx.x >> 5;                      // 0..7
#pragma unroll
    for (int j = 0; j < 32; j += 8)
        tile[ty + j][tx] = feat[((size_t)b * CQ + (c0 + ty + j)) * NQ + (n0 + tx)];
    __syncthreads();
#pragma unroll
    for (int j = 0; j < 32; j += 8)
        g_featT[((size_t)b * NQ + (n0 + ty + j)) * CQ + (c0 + tx)] = tile[tx][ty + j];
}

// ---------------------------------------------------------------------------
// K1: blocks 0..HB-1 = pack + histogram for points AND centers;
//     rest = ALL transpose tiles
// ---------------------------------------------------------------------------
__global__ __launch_bounds__(256)
void k1_hist(const float* __restrict__ xyz,
             const float* __restrict__ new_xyz,
             const float* __restrict__ feat) {
    if (blockIdx.x < HB) {
        int i = blockIdx.x * (BQ * NQ / HB) + threadIdx.x;
        int end = (blockIdx.x + 1) * (BQ * NQ / HB);
        for (; i < end; i += 256) {
            float x = xyz[3 * i + 0], y = xyz[3 * i + 1], z = xyz[3 * i + 2];
            int cell = (cell_of(z) * 10 + cell_of(y)) * 10 + cell_of(x);
            g_xyzp[i] = make_float4(x, y, z, __int_as_float(cell));
            atomicAdd(&g_cellcnt[(i >> 14) * NCELL + cell], 1);
        }
        if (threadIdx.x < CPB) {                    // centers: 128/block, guarded
            int j = blockIdx.x * CPB + threadIdx.x;
            float x = new_xyz[3 * j + 0], y = new_xyz[3 * j + 1], z = new_xyz[3 * j + 2];
            int cell = (cell_of(z) * 10 + cell_of(y)) * 10 + cell_of(x);
            g_cxyz[j] = make_float4(x, y, z, __int_as_float(cell));
            atomicAdd(&g_ccnt[(j >> 12) * NCELL + cell], 1);
        }
    } else {
        transpose_tile(feat, blockIdx.x - HB);
    }
}

// ---------------------------------------------------------------------------
// K2: 4 blocks. 0,1 = point-cell scan; 2,3 = center-cell scan. Re-zeroes.
// ---------------------------------------------------------------------------
__global__ __launch_bounds__(256)
void k2_scan() {
    __shared__ int wsum[8], wbase[8];
    const int which = blockIdx.x >> 1;
    const int b = blockIdx.x & 1;
    const int t = threadIdx.x;
    const int lane = t & 31, wid = t >> 5;

    int* cnt  = (which ? g_ccnt  : g_cellcnt) + b * NCELL;
    int* fill = (which ? g_cfill : g_cellfill) + b * NCELL;

    int cnt4[4];
    int own = 0;
    if (t < 250) {
#pragma unroll
        for (int j = 0; j < 4; j++) { cnt4[j] = cnt[4 * t + j]; own += cnt4[j]; }
    }
    int inc = own;
#pragma unroll
    for (int d = 1; d < 32; d <<= 1) {
        int v = __shfl_up_sync(0xffffffffu, inc, d);
        if (lane >= d) inc += v;
    }
    if (lane == 31) wsum[wid] = inc;
    __syncthreads();
    if (t == 0) {
        int run = 0;
#pragma unroll
        for (int w = 0; w < 8; w++) { wbase[w] = run; run += wsum[w]; }
    }
    __syncthreads();
    if (t < 250) {
        int run = wbase[wid] + inc - own;
#pragma unroll
        for (int j = 0; j < 4; j++) {
            int bin = 4 * t + j;
            if (which == 0) g_cellstart[b * (NCELL + 1) + bin] = run;
            fill[bin] = run;
            cnt[bin] = 0;
            run += cnt4[j];
        }
    }
    if (t == 0 && which == 0) g_cellstart[b * (NCELL + 1) + NCELL] = NQ;
}

// ---------------------------------------------------------------------------
// K3: scatter points and centers into cell order
// ---------------------------------------------------------------------------
__global__ __launch_bounds__(256)
void k3_scatter() {
    int i = blockIdx.x * (BQ * NQ / HB) + threadIdx.x;
    int end = (blockIdx.x + 1) * (BQ * NQ / HB);
    for (; i < end; i += 256) {
        float4 p = g_xyzp[i];
        int cell = __float_as_int(p.w);
        int b = i >> 14, n = i & (NQ - 1);
        int pos = atomicAdd(&g_cellfill[b * NCELL + cell], 1);
        g_sorted[b * NQ + pos] = make_float4(p.x, p.y, p.z, __int_as_float(n));
    }
    if (threadIdx.x < CPB) {
        int j = blockIdx.x * CPB + threadIdx.x;
        float4 p = g_cxyz[j];
        int cell = __float_as_int(p.w);
        int b = j >> 12, s = j & (SQ - 1);
        int pos = atomicAdd(&g_cfill[b * NCELL + cell], 1);
        g_csorted[b * SQ + pos] = make_float4(p.x, p.y, p.z, __int_as_float(s));
    }
}

// ---------------------------------------------------------------------------
// K4: fused ball query + grouping, TWO sorted-adjacent centers per warp.
// Each candidate is loaded once and tested against both centers -> candidate
// load traffic and loop overhead per center halved. Two transposed bitmasks
// per warp; extraction runs per center (identical semantics).
// ---------------------------------------------------------------------------
__global__ __launch_bounds__(WARPS_Q * 32)
void query_group_kernel(float* __restrict__ out) {
    // union: Phase A masks (4 warps x 2 x 2KB = 16KB) / Phase B stage (17.4KB)
    __shared__ __align__(16) float4 stage[2][32 * STP];
    __shared__ int shidx[CENTERS_PB][NS];
    __shared__ int sh_s[CENTERS_PB];

    const int tid  = threadIdx.x;
    const int warp = tid >> 5;
    const int lane = tid & 31;
    const int cbase = blockIdx.x * CENTERS_PB + warp * 2;   // sorted slot of center 0
    const int b = cbase / SQ;                   // pair same batch (SQ even)
    const size_t chan_stride = (size_t)SQ * NS;

    // ---------------- Phase A: paired ball query ----------------
    {
        unsigned* mask0 = (unsigned*)stage + warp * (2 * MW);
        unsigned* mask1 = mask0 + MW;

        float4 cp0 = g_csorted[cbase];
        float4 cp1 = g_csorted[cbase + 1];
        const float r2 = (float)(0.1 * 0.1);
        if (lane == 0) { sh_s[warp * 2] = __float_as_int(cp0.w);
                         sh_s[warp * 2 + 1] = __float_as_int(cp1.w); }

        {   // zero both masks: 8 uint4 rounds
            uint4* m4 = (uint4*)mask0;
#pragma unroll
            for (int i = lane; i < 2 * MW / 4; i += 32) m4[i] = make_uint4(0, 0, 0, 0);
        }
        __syncwarp();

        // union of the two guard-banded cell boxes
        const float xlo = fminf(cp0.x, cp1.x), xhi = fmaxf(cp0.x, cp1.x);
        const float ylo = fminf(cp0.y, cp1.y), yhi = fmaxf(cp0.y, cp1.y);
        const float zlo = fminf(cp0.z, cp1.z), zhi = fmaxf(cp0.z, cp1.z);
        const int x0 = max(0, (int)floorf((xlo - 0.1f) * 10.0f - 0.002f));
        const int x1 = min(9, (int)floorf((xhi + 0.1f) * 10.0f + 0.002f));
        const int y0 = max(0, (int)floorf((ylo - 0.1f) * 10.0f - 0.002f));
        const int y1 = min(9, (int)floorf((yhi + 0.1f) * 10.0f + 0.002f));
        const int z0 = max(0, (int)floorf((zlo - 0.1f) * 10.0f - 0.002f));
        const int z1 = min(9, (int)floorf((zhi + 0.1f) * 10.0f + 0.002f));

        const float4* __restrict__ srt = g_sorted + (size_t)b * NQ;
        const int* __restrict__ cs = g_cellstart + b * (NCELL + 1);

        for (int zc = z0; zc <= z1; zc++) {
            for (int yc = y0; yc <= y1; yc++) {
                int rowbase = (zc * 10 + yc) * 10;
                int st = cs[rowbase + x0];
                int en = cs[rowbase + x1 + 1];
                // branch-free: tail lanes clamp (duplicate OR idempotent)
                for (int ibase = st; ibase < en; ibase += 32) {
                    int i = min(ibase + lane, en - 1);
                    float4 p = srt[i];
                    float dx0 = __fadd_rn(cp0.x, -p.x);
                    float dy0 = __fadd_rn(cp0.y, -p.y);
                    float dz0 = __fadd_rn(cp0.z, -p.z);
                    float d20 = __fadd_rn(__fadd_rn(__fmul_rn(dx0, dx0), __fmul_rn(dy0, dy0)),
                                          __fmul_rn(dz0, dz0));
                    float dx1 = __fadd_rn(cp1.x, -p.x);
                    float dy1 = __fadd_rn(cp1.y, -p.y);
                    float dz1 = __fadd_rn(cp1.z, -p.z);
                    float d21 = __fadd_rn(__fadd_rn(__fmul_rn(dx1, dx1), __fmul_rn(dy1, dy1)),
                                          __fmul_rn(dz1, dz1));
                    int oi = __float_as_int(p.w);
                    int w  = oi >> 5;
                    int slot = ((w & 15) << 5) + (w >> 4);      // transposed slot
                    unsigned bit = 1u << (oi & 31);
                    if (d20 < r2) atomicOr(&mask0[slot], bit);
                    if (d21 < r2) atomicOr(&mask1[slot], bit);
                }
            }
        }
        __syncwarp();

        // per-center extraction (conflict-free, ascending original index)
#pragma unroll
        for (int h = 0; h < 2; h++) {
            unsigned* mask = h ? mask1 : mask0;
            const float ccx = h ? cp1.x : cp0.x;
            const float ccy = h ? cp1.y : cp0.y;
            const float ccz = h ? cp1.z : cp0.z;
            int* sx = shidx[warp * 2 + h];

            unsigned wreg[16];
            int pc = 0;
#pragma unroll
            for (int j = 0; j < 16; j++) {
                wreg[j] = mask[(j << 5) + lane];
                pc += __popc(wreg[j]);
            }
            int inc = pc;
#pragma unroll
            for (int d = 1; d < 32; d <<= 1) {
                int v = __shfl_up_sync(0xffffffffu, inc, d);
                if (lane >= d) inc += v;
            }
            const int cnt  = __shfl_sync(0xffffffffu, inc, 31);
            const int excl = inc - pc;
            if (pc > 0 && excl < NS) {
                int pos = excl;
                int basei = lane * 512;
#pragma unroll
                for (int j = 0; j < 16; j++) {
                    unsigned w = wreg[j];
                    while (w && pos < NS) {
                        int bpos = __ffs(w) - 1;
                        w &= w - 1;
                        sx[pos++] = basei + (j << 5) + bpos;
                    }
                }
            }
            __syncwarp();

            int myidx = (cnt == 0) ? 0 : sx[(lane < cnt) ? lane : 0];
            __syncwarp();
            sx[lane] = myidx;

            // grouped_xyz channels 0..2 (coalesced over lane=k)
            const int s = sh_s[warp * 2 + h];
            float4 p = g_xyzp[(size_t)b * NQ + myidx];
            float* ob = out + ((size_t)b * OUTC * SQ + s) * NS + lane;
            __stcs(ob + 0 * chan_stride, __fadd_rn(p.x, -ccx));
            __stcs(ob + 1 * chan_stride, __fadd_rn(p.y, -ccy));
            __stcs(ob + 2 * chan_stride, __fadd_rn(p.z, -ccz));
        }
    }
    __syncthreads();   // masks dead; shidx + sh_s finalized for all 8 centers

    // ---------------- Phase B: ping-pong grouping, 128 threads -------------
    const int r8 = tid >> 4;                        // 0..7
    const int c4 = tid & 15;                        // 0..15
    const int k  = tid & 31;

    const float4* __restrict__ ft4 =
        (const float4*)(g_featT + (size_t)b * NQ * CQ);

    float4 v0 = __ldg(ft4 + (size_t)shidx[0][r8]      * 16 + c4);
    float4 v1 = __ldg(ft4 + (size_t)shidx[0][r8 + 8]  * 16 + c4);
    float4 v2 = __ldg(ft4 + (size_t)shidx[0][r8 + 16] * 16 + c4);
    float4 v3 = __ldg(ft4 + (size_t)shidx[0][r8 + 24] * 16 + c4);

#pragma unroll 1
    for (int c = 0; c < CENTERS_PB; c++) {
        float4* stg = stage[c & 1];
        stg[r8 * STP + c4]        = v0;
        stg[(r8 + 8) * STP + c4]  = v1;
        stg[(r8 + 16) * STP + c4] = v2;
        stg[(r8 + 24) * STP + c4] = v3;
        __syncthreads();                            // only barrier per center

        if (c + 1 < CENTERS_PB) {                   // prefetch next center
            v0 = __ldg(ft4 + (size_t)shidx[c + 1][r8]      * 16 + c4);
            v1 = __ldg(ft4 + (size_t)shidx[c + 1][r8 + 8]  * 16 + c4);
            v2 = __ldg(ft4 + (size_t)shidx[c + 1][r8 + 16] * 16 + c4);
            v3 = __ldg(ft4 + (size_t)shidx[c + 1][r8 + 24] * 16 + c4);
        }

        // write channels 3..66: warp w covers float4-groups {w, w+4, w+8, w+12}
        const int sc = sh_s[c];
        float* ob = out + ((size_t)b * OUTC * SQ + sc) * NS + k + 3 * chan_stride;
#pragma unroll
        for (int j = 0; j < 4; j++) {
            int cc = warp + j * 4;
            float4 v = stg[k * STP + cc];
            float* o = ob + (size_t)(4 * cc) * chan_stride;
            __stcs(o + 0 * chan_stride, v.x);
            __stcs(o + 1 * chan_stride, v.y);
            __stcs(o + 2 * chan_stride, v.z);
            __stcs(o + 3 * chan_stride, v.w);
        }
        // ping-pong: buffer reuse at c+2 ordered by the c+1 barrier
    }
}

// ---------------------------------------------------------------------------
// Launch
// ---------------------------------------------------------------------------
extern "C" void kernel_launch(void* const* d_in, const int* in_sizes, int n_in,
                              void* d_out, int out_size) {
    const float* xyz     = (const float*)d_in[0];   // [B,N,3]
    const float* new_xyz = (const float*)d_in[1];   // [B,S,3]
    const float* feat    = (const float*)d_in[2];   // [B,C,N]
    float* out = (float*)d_out;                     // [B,67,S,NS]

    k1_hist<<<HB + NTILE, 256>>>(xyz, new_xyz, feat);
    k2_scan<<<2 * BQ, 256>>>();
    k3_scatter<<<HB, 256>>>();

    query_group_kernel<<<QBLOCKS, WARPS_Q * 32>>>(out);
}

// round 17
// speedup vs baseline: 1.7115x; 1.7115x over previous
#include <cuda_runtime.h>
#include <stdint.h>

// Fixed problem shapes
#define BQ 2
#define NQ 16384
#define SQ 4096
#define CQ 64
#define NS 32
#define OUTC 67
#define NCELL 1000            // 10x10x10 grid, cell = radius = 0.1
#define WARPS_B 8             // centers per query block
#define HB 64                 // wide hist/scatter blocks
#define NTILE 2048            // transpose tiles (512 n x 2 c x 2 b)
#define QBLOCKS (BQ * SQ / WARPS_B)   // 1024 query blocks
#define STP 17                // float4 row pitch in stage (conflict-free)
#define CPB (BQ * SQ / HB)    // centers per hist/scatter block = 128
#define MW (NQ / 32)          // mask words per center = 512
#define MAXSEG 20             // guard-banded ranges: up to 4x4=16 row segments

// Device scratch (no allocations allowed). Count arrays start zero (static
// init) and are re-zeroed by k2 each replay -> stateless under graph replay.
__device__ float4 g_xyzp[BQ * NQ];                  // packed xyz, cell id in .w
__device__ float4 g_sorted[BQ * NQ];                // cell-sorted xyz, orig idx in .w
__device__ float4 g_cxyz[BQ * SQ];                  // packed centers, cell id in .w
__device__ float4 g_csorted[BQ * SQ];               // cell-sorted centers, orig s in .w
__device__ float  g_featT[(size_t)BQ * NQ * CQ];    // features [B,N,C]
__device__ int    g_cellcnt[BQ * NCELL];            // point histogram
__device__ int    g_cellstart[BQ * (NCELL + 1)];    // point exclusive prefix
__device__ int    g_cellfill[BQ * NCELL];           // point scatter cursors
__device__ int    g_ccnt[BQ * NCELL];               // center histogram
__device__ int    g_cfill[BQ * NCELL];              // center scatter cursors

__device__ __forceinline__ int cell_of(float v) {
    int c = (int)(v * 10.0f);
    return min(9, max(0, c));
}

// one 32x32 transpose tile of [B,C,N] -> [B,N,C]; id in [0, NTILE)
// Vectorized: float4 global reads and writes; pitch-33 scalar smem bridge.
__device__ __forceinline__ void transpose_tile(const float* __restrict__ feat, int id) {
    __shared__ float tile[32 * 33];
    int n0 = (id & 511) * 32;
    int c0 = ((id >> 9) & 1) * 32;
    int b  = id >> 10;
    int t  = threadIdx.x;

    {   // read: thread (c = t>>3, n4 = t&7) loads float4 along n
        int c  = t >> 3;
        int n4 = t & 7;
        const float4* src = (const float4*)(feat + ((size_t)b * CQ + (c0 + c)) * NQ + n0);
        float4 v = __ldg(src + n4);
        int nb = 4 * n4;
        tile[(nb + 0) * 33 + c] = v.x;
        tile[(nb + 1) * 33 + c] = v.y;
        tile[(nb + 2) * 33 + c] = v.z;
        tile[(nb + 3) * 33 + c] = v.w;
    }
    __syncthreads();
    {   // write: thread (n = t>>3, u = t&7) stores float4 along c
        int n = t >> 3;
        int u = t & 7;
        float4 v;
        v.x = tile[n * 33 + 4 * u + 0];
        v.y = tile[n * 33 + 4 * u + 1];
        v.z = tile[n * 33 + 4 * u + 2];
        v.w = tile[n * 33 + 4 * u + 3];
        float4* dst = (float4*)(g_featT + ((size_t)b * NQ + (n0 + n)) * CQ + c0);
        dst[u] = v;
    }
}

// ---------------------------------------------------------------------------
// K1: blocks 0..HB-1 = pack + histogram for points AND centers;
//     rest = ALL transpose tiles
// ---------------------------------------------------------------------------
__global__ __launch_bounds__(256)
void k1_hist(const float* __restrict__ xyz,
             const float* __restrict__ new_xyz,
             const float* __restrict__ feat) {
    if (blockIdx.x < HB) {
        int i = blockIdx.x * (BQ * NQ / HB) + threadIdx.x;
        int end = (blockIdx.x + 1) * (BQ * NQ / HB);
        for (; i < end; i += 256) {
            float x = xyz[3 * i + 0], y = xyz[3 * i + 1], z = xyz[3 * i + 2];
            int cell = (cell_of(z) * 10 + cell_of(y)) * 10 + cell_of(x);
            g_xyzp[i] = make_float4(x, y, z, __int_as_float(cell));
            atomicAdd(&g_cellcnt[(i >> 14) * NCELL + cell], 1);
        }
        if (threadIdx.x < CPB) {                    // centers: 128/block, guarded
            int j = blockIdx.x * CPB + threadIdx.x;
            float x = new_xyz[3 * j + 0], y = new_xyz[3 * j + 1], z = new_xyz[3 * j + 2];
            int cell = (cell_of(z) * 10 + cell_of(y)) * 10 + cell_of(x);
            g_cxyz[j] = make_float4(x, y, z, __int_as_float(cell));
            atomicAdd(&g_ccnt[(j >> 12) * NCELL + cell], 1);
        }
    } else {
        transpose_tile(feat, blockIdx.x - HB);
    }
}

// ---------------------------------------------------------------------------
// K2: 4 blocks. 0,1 = point-cell scan; 2,3 = center-cell scan. Re-zeroes.
// ---------------------------------------------------------------------------
__global__ __launch_bounds__(256)
void k2_scan() {
    __shared__ int wsum[8], wbase[8];
    const int which = blockIdx.x >> 1;
    const int b = blockIdx.x & 1;
    const int t = threadIdx.x;
    const int lane = t & 31, wid = t >> 5;

    int* cnt  = (which ? g_ccnt  : g_cellcnt) + b * NCELL;
    int* fill = (which ? g_cfill : g_cellfill) + b * NCELL;

    int cnt4[4];
    int own = 0;
    if (t < 250) {
#pragma unroll
        for (int j = 0; j < 4; j++) { cnt4[j] = cnt[4 * t + j]; own += cnt4[j]; }
    }
    int inc = own;
#pragma unroll
    for (int d = 1; d < 32; d <<= 1) {
        int v = __shfl_up_sync(0xffffffffu, inc, d);
        if (lane >= d) inc += v;
    }
    if (lane == 31) wsum[wid] = inc;
    __syncthreads();
    if (t == 0) {
        int run = 0;
#pragma unroll
        for (int w = 0; w < 8; w++) { wbase[w] = run; run += wsum[w]; }
    }
    __syncthreads();
    if (t < 250) {
        int run = wbase[wid] + inc - own;
#pragma unroll
        for (int j = 0; j < 4; j++) {
            int bin = 4 * t + j;
            if (which == 0) g_cellstart[b * (NCELL + 1) + bin] = run;
            fill[bin] = run;
            cnt[bin] = 0;
            run += cnt4[j];
        }
    }
    if (t == 0 && which == 0) g_cellstart[b * (NCELL + 1) + NCELL] = NQ;
}

// ---------------------------------------------------------------------------
// K3: scatter points and centers into cell order
// ---------------------------------------------------------------------------
__global__ __launch_bounds__(256)
void k3_scatter() {
    int i = blockIdx.x * (BQ * NQ / HB) + threadIdx.x;
    int end = (blockIdx.x + 1) * (BQ * NQ / HB);
    for (; i < end; i += 256) {
        float4 p = g_xyzp[i];
        int cell = __float_as_int(p.w);
        int b = i >> 14, n = i & (NQ - 1);
        int pos = atomicAdd(&g_cellfill[b * NCELL + cell], 1);
        g_sorted[b * NQ + pos] = make_float4(p.x, p.y, p.z, __int_as_float(n));
    }
    if (threadIdx.x < CPB) {
        int j = blockIdx.x * CPB + threadIdx.x;
        float4 p = g_cxyz[j];
        int cell = __float_as_int(p.w);
        int b = j >> 12, s = j & (SQ - 1);
        int pos = atomicAdd(&g_cfill[b * NCELL + cell], 1);
        g_csorted[b * SQ + pos] = make_float4(p.x, p.y, p.z, __int_as_float(s));
    }
}

// ---------------------------------------------------------------------------
// K4: fused ball query + grouping.
// Phase A per warp: FLATTENED candidate loop over a <=16 segment table
//   (MAXSEG=20 with margin), transposed bitmask, conflict-free extraction.
// Phase B block-cooperative: ping-pong double-buffered staging.
// ---------------------------------------------------------------------------
__global__ __launch_bounds__(256)
void query_group_kernel(float* __restrict__ out) {
    __shared__ __align__(16) float4 stage[2][32 * STP];   // 17.4KB; masks alias
    __shared__ int shidx[WARPS_B][NS];
    __shared__ int sh_s[WARPS_B];
    __shared__ int seg_adj[WARPS_B][MAXSEG];        // i = pos + adj within segment
    __shared__ int seg_cum[WARPS_B][MAXSEG];        // cumulative end of segment

    const int tid  = threadIdx.x;
    const int warp = tid >> 5;
    const int lane = tid & 31;
    const int csort = blockIdx.x * WARPS_B + warp;
    const int b = csort / SQ;
    const size_t chan_stride = (size_t)SQ * NS;

    // ---------------- Phase A: ball query ----------------
    {
        unsigned* mask = (unsigned*)stage + warp * MW;      // 2KB/warp

        float4 cp = g_csorted[csort];
        const float cx = cp.x, cy = cp.y, cz = cp.z;
        const int   s  = __float_as_int(cp.w);
        const float r2 = (float)(0.1 * 0.1);
        if (lane == 0) sh_s[warp] = s;

        {
            uint4* m4 = (uint4*)mask;
#pragma unroll
            for (int i = lane; i < MW / 4; i += 32) m4[i] = make_uint4(0, 0, 0, 0);
        }

        const int x0 = max(0, (int)floorf((cx - 0.1f) * 10.0f - 0.002f));
        const int x1 = min(9, (int)floorf((cx + 0.1f) * 10.0f + 0.002f));
        const int y0 = max(0, (int)floorf((cy - 0.1f) * 10.0f - 0.002f));
        const int y1 = min(9, (int)floorf((cy + 0.1f) * 10.0f + 0.002f));
        const int z0 = max(0, (int)floorf((cz - 0.1f) * 10.0f - 0.002f));
        const int z1 = min(9, (int)floorf((cz + 0.1f) * 10.0f + 0.002f));

        const float4* __restrict__ srt = g_sorted + (size_t)b * NQ;
        const int* __restrict__ cs = g_cellstart + b * (NCELL + 1);

        // build segment table (uniform across warp; lane 0 writes; <=16 segs)
        int total = 0;
        int nseg  = 0;
        for (int zc = z0; zc <= z1; zc++) {
            for (int yc = y0; yc <= y1; yc++) {
                int rowbase = (zc * 10 + yc) * 10;
                int st = cs[rowbase + x0];
                int en = cs[rowbase + x1 + 1];      // x-contiguous cells
                int len = en - st;
                if (len > 0) {
                    if (lane == 0) {
                        seg_adj[warp][nseg] = st - total;
                        seg_cum[warp][nseg] = total + len;
                    }
                    nseg++;
                    total += len;
                }
            }
        }
        __syncwarp();

        // flattened candidate loop: each lane tracks its segment incrementally
        int seg = 0;
        int adj = seg_adj[warp][0];
        int nxt = seg_cum[warp][0];
        for (int pbase = 0; pbase < total; pbase += 32) {
            int pos = min(pbase + lane, total - 1);     // clamp: duplicate OR ok
            while (pos >= nxt) {
                seg++;
                adj = seg_adj[warp][seg];
                nxt = seg_cum[warp][seg];
            }
            float4 p = srt[pos + adj];
            float dx = __fadd_rn(cx, -p.x);
            float dy = __fadd_rn(cy, -p.y);
            float dz = __fadd_rn(cz, -p.z);
            float d2 = __fadd_rn(__fadd_rn(__fmul_rn(dx, dx), __fmul_rn(dy, dy)),
                                 __fmul_rn(dz, dz));
            int oi = __float_as_int(p.w);
            int w  = oi >> 5;
            int slot = ((w & 15) << 5) + (w >> 4);      // transposed slot
            if (d2 < r2) atomicOr(&mask[slot], 1u << (oi & 31));
        }
        __syncwarp();

        // conflict-free single-pass extraction (ascending original index)
        unsigned wreg[16];
        int pc = 0;
#pragma unroll
        for (int j = 0; j < 16; j++) {
            wreg[j] = mask[(j << 5) + lane];
            pc += __popc(wreg[j]);
        }
        int inc = pc;
#pragma unroll
        for (int d = 1; d < 32; d <<= 1) {
            int v = __shfl_up_sync(0xffffffffu, inc, d);
            if (lane >= d) inc += v;
        }
        const int cnt  = __shfl_sync(0xffffffffu, inc, 31);
        const int excl = inc - pc;
        if (pc > 0 && excl < NS) {
            int pos = excl;
            int basei = lane * 512;
#pragma unroll
            for (int j = 0; j < 16; j++) {
                unsigned w = wreg[j];
                while (w && pos < NS) {
                    int bpos = __ffs(w) - 1;
                    w &= w - 1;
                    shidx[warp][pos++] = basei + (j << 5) + bpos;
                }
            }
        }
        __syncwarp();

        int myidx = (cnt == 0) ? 0 : shidx[warp][(lane < cnt) ? lane : 0];
        __syncwarp();
        shidx[warp][lane] = myidx;

        // grouped_xyz channels 0..2 (coalesced over lane=k)
        float4 p = g_xyzp[(size_t)b * NQ + myidx];
        float* ob = out + ((size_t)b * OUTC * SQ + s) * NS + lane;
        __stcs(ob + 0 * chan_stride, __fadd_rn(p.x, -cx));
        __stcs(ob + 1 * chan_stride, __fadd_rn(p.y, -cy));
        __stcs(ob + 2 * chan_stride, __fadd_rn(p.z, -cz));
    }
    __syncthreads();   // masks dead; shidx + sh_s finalized for all warps

    // ---------------- Phase B: ping-pong double-buffered grouping ----------
    const int r  = tid >> 4;                        // 0..15
    const int c4 = tid & 15;                        // 0..15
    const int k  = tid & 31;
    const int w  = tid >> 5;                        // 0..7

    const float4* __restrict__ ft4 =
        (const float4*)(g_featT + (size_t)b * NQ * CQ);

    float4 v0 = __ldg(ft4 + (size_t)shidx[0][r]      * 16 + c4);
    float4 v1 = __ldg(ft4 + (size_t)shidx[0][r + 16] * 16 + c4);

#pragma unroll 1
    for (int c = 0; c < WARPS_B; c++) {
        float4* stg = stage[c & 1];
        stg[r * STP + c4]        = v0;
        stg[(r + 16) * STP + c4] = v1;
        __syncthreads();                            // only barrier per center

        if (c + 1 < WARPS_B) {                      // prefetch next center
            v0 = __ldg(ft4 + (size_t)shidx[c + 1][r]      * 16 + c4);
            v1 = __ldg(ft4 + (size_t)shidx[c + 1][r + 16] * 16 + c4);
        }

        // write channels 3..66: lane=k coalesced 128B stores
        const int sc = sh_s[c];
        float* ob = out + ((size_t)b * OUTC * SQ + sc) * NS + k + 3 * chan_stride;
#pragma unroll
        for (int cc = w; cc < 16; cc += 8) {
            float4 v = stg[k * STP + cc];
            float* o = ob + (size_t)(4 * cc) * chan_stride;
            __stcs(o + 0 * chan_stride, v.x);
            __stcs(o + 1 * chan_stride, v.y);
            __stcs(o + 2 * chan_stride, v.z);
            __stcs(o + 3 * chan_stride, v.w);
        }
        // ping-pong: buffer reuse at c+2 ordered by the c+1 barrier
    }
}

// ---------------------------------------------------------------------------
// Launch
// ---------------------------------------------------------------------------
extern "C" void kernel_launch(void* const* d_in, const int* in_sizes, int n_in,
                              void* d_out, int out_size) {
    const float* xyz     = (const float*)d_in[0];   // [B,N,3]
    const float* new_xyz = (const float*)d_in[1];   // [B,S,3]
    const float* feat    = (const float*)d_in[2];   // [B,C,N]
    float* out = (float*)d_out;                     // [B,67,S,NS]

    k1_hist<<<HB + NTILE, 256>>>(xyz, new_xyz, feat);
    k2_scan<<<2 * BQ, 256>>>();
    k3_scatter<<<HB, 256>>>();

    query_group_kernel<<<QBLOCKS, 256>>>(out);
}